// round 14
// baseline (speedup 1.0000x reference)
#include <cuda_runtime.h>
#include <cuda_fp16.h>
#include <cstdint>

#define NB   4
#define NH   16
#define SEQ  2048
#define DMOD 1024
#define DH   64
#define BHN  (NB * NH)        // 64
#define SL   4194304          // floats per attn slice (2048*2048)
#define PBH  131072           // ELEMENTS per (bh) Q/K/V slab (2048*64), fp16
#define NSPLIT 58             // bh 0..57 staged in d_out, 58..63 in g_tail

// Scratch: 6 tail (bh) Q/K/V slabs (4.7 MB, fp16) + row sums (0.5 MB).
static __device__ __half g_tail[18 * PBH];
static __device__ float g_sums[(size_t)BHN * SEQ];

// ---------------------------------------------------------------------------
// helpers
// ---------------------------------------------------------------------------
__device__ __forceinline__ uint32_t pack_h2(float lo, float hi) {
    __half2 h = __floats2half2_rn(lo, hi);
    return *reinterpret_cast<uint32_t*>(&h);
}

__device__ __forceinline__ void mma_f16(float* c, const uint32_t* a, const uint32_t* b) {
    asm volatile(
        "mma.sync.aligned.m16n8k16.row.col.f32.f16.f16.f32 "
        "{%0,%1,%2,%3}, {%4,%5,%6,%7}, {%8,%9}, {%0,%1,%2,%3};"
        : "+f"(c[0]), "+f"(c[1]), "+f"(c[2]), "+f"(c[3])
        : "r"(a[0]), "r"(a[1]), "r"(a[2]), "r"(a[3]), "r"(b[0]), "r"(b[1]));
}

__device__ __forceinline__ void cp16(uint32_t smem_addr, const void* g) {
    asm volatile("cp.async.ca.shared.global [%0], [%1], 16;"
                 :: "r"(smem_addr), "l"(g));
}
#define CP_COMMIT() asm volatile("cp.async.commit_group;")
#define CP_WAIT0()  asm volatile("cp.async.wait_group 0;")

// ---------------------------------------------------------------------------
// Kernel 1: fused QKV projection, fp16 m16n8k16 (fp32 accum).
// Block 128x128, K-tile 16, 8 warps (2x4), warp tile 64x32.
// X staged as raw fp16 rows [128][16h]; W transpose-staged to [n][16h].
// Fragment conventions identical to the fused kernel (validated).
// Q/K written as fp16 (s,d) rows; V PRE-INTERLEAVED half2 key-pairs.
// ---------------------------------------------------------------------------
#define PS 12   // proj smem row stride in words (8 data + 4 pad; conflict-free)

__global__ __launch_bounds__(256) void proj_kernel(
    const float* __restrict__ xq, const float* __restrict__ xk, const float* __restrict__ xv,
    const float* __restrict__ wq, const float* __restrict__ wk, const float* __restrict__ wv,
    const float* __restrict__ bq, const float* __restrict__ bk, const float* __restrict__ bv,
    __half* __restrict__ stage)
{
    const int which = blockIdx.z;
    const float* X  = (which == 0) ? xq : (which == 1) ? xk : xv;
    const float* W  = (which == 0) ? wq : (which == 1) ? wk : wv;
    const float* Bi = (which == 0) ? bq : (which == 1) ? bk : bv;

    __shared__ uint32_t Xs[128 * PS];   // [row][8 words = 16 halves k]
    __shared__ uint32_t Ws[128 * PS];   // [n][8 words = 16 halves k]

    const int tid  = threadIdx.x;
    const int warp = tid >> 5;
    const int lane = tid & 31;
    const int gr   = lane >> 2;
    const int tg   = lane & 3;

    const int m0 = blockIdx.y * 128;
    const int n0 = blockIdx.x * 128;
    const int warp_m = (warp >> 2) * 64;
    const int warp_n = (warp & 3) * 32;

    // X loader: row, half-offset (0 or 8)
    const int a_r  = tid >> 1;
    const int a_kc = (tid & 1) * 8;
    // W loader: k-row 0..15, n-base 0..120
    const int w_kr = tid & 15;
    const int w_nb = (tid >> 4) * 8;

    __half* Wsh = (__half*)Ws;

    float acc[4][4][4];
#pragma unroll
    for (int mt = 0; mt < 4; mt++)
#pragma unroll
        for (int nt = 0; nt < 4; nt++)
#pragma unroll
            for (int r = 0; r < 4; r++) acc[mt][nt][r] = 0.f;

    for (int k0 = 0; k0 < DMOD; k0 += 16) {
        float4 x0 = *(const float4*)&X[(size_t)(m0 + a_r) * DMOD + k0 + a_kc];
        float4 x1 = *(const float4*)&X[(size_t)(m0 + a_r) * DMOD + k0 + a_kc + 4];
        float4 w0 = *(const float4*)&W[(size_t)(k0 + w_kr) * DMOD + n0 + w_nb];
        float4 w1 = *(const float4*)&W[(size_t)(k0 + w_kr) * DMOD + n0 + w_nb + 4];
        __syncthreads();
        {
            uint4 u = make_uint4(pack_h2(x0.x, x0.y), pack_h2(x0.z, x0.w),
                                 pack_h2(x1.x, x1.y), pack_h2(x1.z, x1.w));
            *(uint4*)&Xs[a_r * PS + a_kc / 2] = u;
        }
        Wsh[(w_nb + 0) * (2 * PS) + w_kr] = __float2half(w0.x);
        Wsh[(w_nb + 1) * (2 * PS) + w_kr] = __float2half(w0.y);
        Wsh[(w_nb + 2) * (2 * PS) + w_kr] = __float2half(w0.z);
        Wsh[(w_nb + 3) * (2 * PS) + w_kr] = __float2half(w0.w);
        Wsh[(w_nb + 4) * (2 * PS) + w_kr] = __float2half(w1.x);
        Wsh[(w_nb + 5) * (2 * PS) + w_kr] = __float2half(w1.y);
        Wsh[(w_nb + 6) * (2 * PS) + w_kr] = __float2half(w1.z);
        Wsh[(w_nb + 7) * (2 * PS) + w_kr] = __float2half(w1.w);
        __syncthreads();

        uint32_t af[4][4], bf[4][2];
#pragma unroll
        for (int mt = 0; mt < 4; mt++) {
            const int mm = warp_m + mt * 16 + gr;
            af[mt][0] = Xs[mm * PS + tg];
            af[mt][1] = Xs[(mm + 8) * PS + tg];
            af[mt][2] = Xs[mm * PS + tg + 4];
            af[mt][3] = Xs[(mm + 8) * PS + tg + 4];
        }
#pragma unroll
        for (int nt = 0; nt < 4; nt++) {
            const int nn = warp_n + nt * 8 + gr;
            bf[nt][0] = Ws[nn * PS + tg];
            bf[nt][1] = Ws[nn * PS + tg + 4];
        }
#pragma unroll
        for (int mt = 0; mt < 4; mt++)
#pragma unroll
            for (int nt = 0; nt < 4; nt++)
                mma_f16(acc[mt][nt], af[mt], bf[nt]);
    }

    const int h  = (n0 + warp_n) >> 6;
    const int bb = m0 >> 11;
    const int bh = bb * NH + h;
    const int d_base = ((n0 + warp_n) & 63);
    const int ss_base = (m0 & (SEQ - 1)) + warp_m;

    __half* dst = (bh < NSPLIT)
        ? stage + (size_t)which * ((size_t)NSPLIT * PBH) + (size_t)bh * PBH
        : g_tail + (size_t)which * (6 * PBH) + (size_t)(bh - NSPLIT) * PBH;

#pragma unroll
    for (int nt = 0; nt < 4; nt++) {
        const int ncol = n0 + warp_n + nt * 8 + 2 * tg;
        const float bias0 = Bi[ncol];
        const float bias1 = Bi[ncol + 1];
        const int d = d_base + nt * 8 + 2 * tg;
#pragma unroll
        for (int mt = 0; mt < 4; mt++) {
            const int s0 = ss_base + mt * 16 + gr;
            const int s1 = s0 + 8;
            if (which == 2) {
                // V: interleaved half2 key-pair layout
                dst[(size_t)(s0 >> 1) * (2 * DH) + 2 * d + (s0 & 1)] =
                    __float2half(acc[mt][nt][0] + bias0);
                dst[(size_t)(s0 >> 1) * (2 * DH) + 2 * (d + 1) + (s0 & 1)] =
                    __float2half(acc[mt][nt][1] + bias1);
                dst[(size_t)(s1 >> 1) * (2 * DH) + 2 * d + (s1 & 1)] =
                    __float2half(acc[mt][nt][2] + bias0);
                dst[(size_t)(s1 >> 1) * (2 * DH) + 2 * (d + 1) + (s1 & 1)] =
                    __float2half(acc[mt][nt][3] + bias1);
            } else {
                __half2 v0 = __floats2half2_rn(acc[mt][nt][0] + bias0, acc[mt][nt][1] + bias1);
                __half2 v1 = __floats2half2_rn(acc[mt][nt][2] + bias0, acc[mt][nt][3] + bias1);
                *(__half2*)&dst[(size_t)s0 * DH + d] = v0;
                *(__half2*)&dst[(size_t)s1 * DH + d] = v1;
            }
        }
    }
}

// ---------------------------------------------------------------------------
// Kernel 2: FUSED attention, all-fp16 tensor ops + cp.async double buffering.
// (unchanged from R13 — validated)
// smem layout (words), per buffer: K[128*36] | V[64*72] | M[128*36]
// ---------------------------------------------------------------------------
#define KW 36
#define VW 72
#define MW 36
#define KBUF (128 * KW)
#define VBUF (64 * VW)
#define MBUF (128 * MW)
#define TBUF (KBUF + VBUF + MBUF)
#define SMEM_WORDS (2 * TBUF)

__global__ __launch_bounds__(256, 2) void fused_attn_kernel(
    const unsigned char* __restrict__ mask, float* __restrict__ attn,
    float* __restrict__ ctx, const __half* __restrict__ stage, int bh0)
{
    extern __shared__ uint32_t smem[];

    const int bh = bh0 + blockIdx.y;
    const int m0 = blockIdx.x * 128;
    const int b = bh >> 4, h = bh & 15;

    const __half* Q = (bh < NSPLIT)
        ? stage + (size_t)bh * PBH
        : g_tail + (size_t)(bh - NSPLIT) * PBH;
    const __half* K = (bh < NSPLIT)
        ? stage + (size_t)NSPLIT * PBH + (size_t)bh * PBH
        : g_tail + (size_t)(6 * PBH) + (size_t)(bh - NSPLIT) * PBH;
    const __half* V = (bh < NSPLIT)
        ? stage + (size_t)(2 * NSPLIT) * PBH + (size_t)bh * PBH
        : g_tail + (size_t)(12 * PBH) + (size_t)(bh - NSPLIT) * PBH;

    const int tid  = threadIdx.x;
    const int warp = tid >> 5;
    const int lane = tid & 31;
    const int gr   = lane >> 2;
    const int tg   = lane & 3;

    const int r0 = warp * 16 + gr;
    const int r1 = r0 + 8;

    const uint32_t smem_base = (uint32_t)__cvta_generic_to_shared(smem);

    uint32_t qf[4][4];
#pragma unroll
    for (int kc = 0; kc < 4; kc++) {
        qf[kc][0] = *(const uint32_t*)&Q[(size_t)(m0 + r0) * DH + (kc * 8 + tg) * 2];
        qf[kc][1] = *(const uint32_t*)&Q[(size_t)(m0 + r1) * DH + (kc * 8 + tg) * 2];
        qf[kc][2] = *(const uint32_t*)&Q[(size_t)(m0 + r0) * DH + (kc * 8 + tg + 4) * 2];
        qf[kc][3] = *(const uint32_t*)&Q[(size_t)(m0 + r1) * DH + (kc * 8 + tg + 4) * 2];
    }

    float rsum0 = 0.f, rsum1 = 0.f;
    float ctxacc[8][4];
#pragma unroll
    for (int dt = 0; dt < 8; dt++)
#pragma unroll
        for (int r = 0; r < 4; r++) ctxacc[dt][r] = 0.f;

    float* arow0 = attn + ((size_t)bh * SEQ + m0 + r0) * SEQ;
    float* arow1 = attn + ((size_t)bh * SEQ + m0 + r1) * SEQ;

    const int k_row = tid >> 1;
    const int k_cw  = (tid & 1) * 16;
    const int v_row = tid >> 2;
    const int v_cw  = (tid & 3) * 16;
    const int m_row = tid >> 1;
    const int m_cb  = (tid & 1) * 64;

    const unsigned char* mask_base = mask + ((size_t)b * SEQ + m0) * SEQ;

    auto load_tile = [&](int kt, int buf) {
        const uint32_t boff = smem_base + buf * (TBUF * 4);
        {
            const __half* src = K + (size_t)(kt * 128 + k_row) * DH + k_cw * 2;
            uint32_t dst = boff + (k_row * KW + k_cw) * 4;
            cp16(dst, src);
            cp16(dst + 16, src + 8);
            cp16(dst + 32, src + 16);
            cp16(dst + 48, src + 24);
        }
        {
            const __half* src = V + (size_t)(kt * 64 + v_row) * (2 * DH) + v_cw * 2;
            uint32_t dst = boff + (KBUF + v_row * VW + v_cw) * 4;
            cp16(dst, src);
            cp16(dst + 16, src + 8);
            cp16(dst + 32, src + 16);
            cp16(dst + 48, src + 24);
        }
        {
            const unsigned char* src = mask_base + (size_t)m_row * SEQ + kt * 128 + m_cb;
            uint32_t dst = boff + (KBUF + VBUF + m_row * MW) * 4 + m_cb;
            cp16(dst, src);
            cp16(dst + 16, src + 16);
            cp16(dst + 32, src + 32);
            cp16(dst + 48, src + 48);
        }
        CP_COMMIT();
    };

    load_tile(0, 0);
    int buf = 0;

    for (int kt = 0; kt < 16; kt++) {
        CP_WAIT0();
        __syncthreads();
        if (kt < 15) load_tile(kt + 1, buf ^ 1);

        const uint32_t* Kh = smem + buf * TBUF;
        const uint32_t* Vh = Kh + KBUF;
        const unsigned char* Mh = (const unsigned char*)(Vh + VBUF);

#pragma unroll
        for (int hk = 0; hk < 2; hk++) {
            const int kbase = hk * 64;

            float sacc[8][4];
#pragma unroll
            for (int nt = 0; nt < 8; nt++)
#pragma unroll
                for (int r = 0; r < 4; r++) sacc[nt][r] = 0.f;

#pragma unroll
            for (int kc = 0; kc < 4; kc++) {
#pragma unroll
                for (int nt = 0; nt < 8; nt++) {
                    uint32_t bf[2];
                    bf[0] = Kh[(kbase + nt * 8 + gr) * KW + kc * 8 + tg];
                    bf[1] = Kh[(kbase + nt * 8 + gr) * KW + kc * 8 + tg + 4];
                    mma_f16(sacc[nt], qf[kc], bf);
                }
            }

            const int colb = kt * 128 + kbase;
#pragma unroll
            for (int nt = 0; nt < 8; nt++) {
                const int lcol = kbase + nt * 8 + 2 * tg;
                const int col  = colb + nt * 8 + 2 * tg;
                uchar2 mm0 = *(const uchar2*)&Mh[(size_t)r0 * (MW * 4) + lcol];
                uchar2 mm1 = *(const uchar2*)&Mh[(size_t)r1 * (MW * 4) + lcol];
                float s00 = mm0.x ? -1e9f : sacc[nt][0] * 0.125f;
                float s01 = mm0.y ? -1e9f : sacc[nt][1] * 0.125f;
                float s10 = mm1.x ? -1e9f : sacc[nt][2] * 0.125f;
                float s11 = mm1.y ? -1e9f : sacc[nt][3] * 0.125f;
                float p00 = __expf(s00), p01 = __expf(s01);
                float p10 = __expf(s10), p11 = __expf(s11);
                rsum0 += p00 + p01;
                rsum1 += p10 + p11;
                sacc[nt][0] = p00; sacc[nt][1] = p01;
                sacc[nt][2] = p10; sacc[nt][3] = p11;
                *(float2*)&arow0[col] = make_float2(p00, p01);
                *(float2*)&arow1[col] = make_float2(p10, p11);
            }

#pragma unroll
            for (int g = 0; g < 4; g++) {
                uint32_t pa[4];
                pa[0] = pack_h2(sacc[2 * g][0],     sacc[2 * g][1]);
                pa[1] = pack_h2(sacc[2 * g][2],     sacc[2 * g][3]);
                pa[2] = pack_h2(sacc[2 * g + 1][0], sacc[2 * g + 1][1]);
                pa[3] = pack_h2(sacc[2 * g + 1][2], sacc[2 * g + 1][3]);
#pragma unroll
                for (int dt = 0; dt < 8; dt++) {
                    uint32_t vb[2];
                    vb[0] = Vh[(hk * 32 + g * 8 + tg) * VW + dt * 8 + gr];
                    vb[1] = Vh[(hk * 32 + g * 8 + tg + 4) * VW + dt * 8 + gr];
                    mma_f16(ctxacc[dt], pa, vb);
                }
            }
        }
        __syncthreads();
        buf ^= 1;
    }

    rsum0 += __shfl_xor_sync(0xffffffffu, rsum0, 1);
    rsum0 += __shfl_xor_sync(0xffffffffu, rsum0, 2);
    rsum1 += __shfl_xor_sync(0xffffffffu, rsum1, 1);
    rsum1 += __shfl_xor_sync(0xffffffffu, rsum1, 2);
    if (tg == 0) {
        g_sums[(size_t)bh * SEQ + m0 + r0] = rsum0;
        g_sums[(size_t)bh * SEQ + m0 + r1] = rsum1;
    }
    const float inv0 = 1.0f / rsum0;
    const float inv1 = 1.0f / rsum1;

    float* crow0 = ctx + ((size_t)b * SEQ + m0 + r0) * DMOD + h * DH;
    float* crow1 = ctx + ((size_t)b * SEQ + m0 + r1) * DMOD + h * DH;
#pragma unroll
    for (int dt = 0; dt < 8; dt++) {
        const int d = dt * 8 + 2 * tg;
        *(float2*)&crow0[d] = make_float2(ctxacc[dt][0] * inv0, ctxacc[dt][1] * inv0);
        *(float2*)&crow1[d] = make_float2(ctxacc[dt][2] * inv1, ctxacc[dt][3] * inv1);
    }
}

// ---------------------------------------------------------------------------
// Kernel 3: scale attn rows by 1/rowsum (at DRAM roofline; unchanged).
// ---------------------------------------------------------------------------
__global__ __launch_bounds__(256) void scale_kernel(float* __restrict__ attn)
{
    const size_t row = blockIdx.x;
    const float inv = 1.0f / g_sums[row];
    float* p = attn + row * SEQ;
    const int tid = threadIdx.x;
    float4 v0 = *(float4*)&p[tid * 4];
    float4 v1 = *(float4*)&p[1024 + tid * 4];
    v0.x *= inv; v0.y *= inv; v0.z *= inv; v0.w *= inv;
    v1.x *= inv; v1.y *= inv; v1.z *= inv; v1.w *= inv;
    *(float4*)&p[tid * 4] = v0;
    *(float4*)&p[1024 + tid * 4] = v1;
}

// ---------------------------------------------------------------------------
// Launch. Output: [context (4,2048,1024) | attn (4,16,2048,2048)] fp32.
// Q/K/V (fp16) for bh<58 staged in attn slices 58..63; bh>=58 in g_tail.
// ---------------------------------------------------------------------------
extern "C" void kernel_launch(void* const* d_in, const int* in_sizes, int n_in,
                              void* d_out, int out_size)
{
    (void)in_sizes; (void)n_in; (void)out_size;
    const float* q  = (const float*)d_in[0];
    const float* k  = (const float*)d_in[1];
    const float* v  = (const float*)d_in[2];
    const unsigned char* mask = (const unsigned char*)d_in[3];
    const float* wq = (const float*)d_in[4];
    const float* wk = (const float*)d_in[5];
    const float* wv = (const float*)d_in[6];
    const float* bq = (const float*)d_in[7];
    const float* bk = (const float*)d_in[8];
    const float* bv = (const float*)d_in[9];

    float* ctx   = (float*)d_out;
    float* attn  = (float*)d_out + (size_t)NB * SEQ * DMOD;
    __half* stage = (__half*)(attn + (size_t)NSPLIT * SL);   // slices 58..63

    const int smem_bytes = SMEM_WORDS * 4;   // 110592 B
    cudaFuncSetAttribute(fused_attn_kernel,
                         cudaFuncAttributeMaxDynamicSharedMemorySize, smem_bytes);

    // 1) QKV projections into fp16 staging (V interleaved)
    {
        dim3 grid(DMOD / 128, (NB * SEQ) / 128, 3);
        proj_kernel<<<grid, 256>>>(q, k, v, wq, wk, wv, bq, bk, bv, stage);
    }
    // 2) Phase A: fused attention for bh 0..57
    {
        dim3 grid(SEQ / 128, NSPLIT);
        fused_attn_kernel<<<grid, 256, smem_bytes>>>(mask, attn, ctx, stage, 0);
    }
    // 3) Phase B: fused attention for bh 58..63 (QKV in g_tail)
    {
        dim3 grid(SEQ / 128, BHN - NSPLIT);
        fused_attn_kernel<<<grid, 256, smem_bytes>>>(mask, attn, ctx, stage, NSPLIT);
    }
    // 4) Normalize the attn output
    scale_kernel<<<BHN * SEQ, 256>>>(attn);
}

// round 15
// speedup vs baseline: 1.0130x; 1.0130x over previous
#include <cuda_runtime.h>
#include <cuda_fp16.h>
#include <cstdint>

#define NB   4
#define NH   16
#define SEQ  2048
#define DMOD 1024
#define DH   64
#define BHN  (NB * NH)        // 64
#define SL   4194304          // floats per attn slice (2048*2048)
#define PBH  131072           // ELEMENTS per (bh) Q/K/V slab (2048*64), fp16
#define NSPLIT 58             // bh 0..57 staged in d_out, 58..63 in g_tail

// Scratch: 6 tail (bh) Q/K/V slabs (4.7 MB, fp16) + row sums (0.5 MB).
static __device__ __half g_tail[18 * PBH];
static __device__ float g_sums[(size_t)BHN * SEQ];

// ---------------------------------------------------------------------------
// helpers
// ---------------------------------------------------------------------------
__device__ __forceinline__ uint32_t f2tf(float f) {
    uint32_t u;
    asm("cvt.rna.tf32.f32 %0, %1;" : "=r"(u) : "f"(f));
    return u;
}

__device__ __forceinline__ uint32_t pack_h2(float lo, float hi) {
    __half2 h = __floats2half2_rn(lo, hi);
    return *reinterpret_cast<uint32_t*>(&h);
}

__device__ __forceinline__ void mma_tf32(float* c, const uint32_t* a, const uint32_t* b) {
    asm volatile(
        "mma.sync.aligned.m16n8k8.row.col.f32.tf32.tf32.f32 "
        "{%0,%1,%2,%3}, {%4,%5,%6,%7}, {%8,%9}, {%0,%1,%2,%3};"
        : "+f"(c[0]), "+f"(c[1]), "+f"(c[2]), "+f"(c[3])
        : "r"(a[0]), "r"(a[1]), "r"(a[2]), "r"(a[3]), "r"(b[0]), "r"(b[1]));
}

__device__ __forceinline__ void mma_f16(float* c, const uint32_t* a, const uint32_t* b) {
    asm volatile(
        "mma.sync.aligned.m16n8k16.row.col.f32.f16.f16.f32 "
        "{%0,%1,%2,%3}, {%4,%5,%6,%7}, {%8,%9}, {%0,%1,%2,%3};"
        : "+f"(c[0]), "+f"(c[1]), "+f"(c[2]), "+f"(c[3])
        : "r"(a[0]), "r"(a[1]), "r"(a[2]), "r"(a[3]), "r"(b[0]), "r"(b[1]));
}

__device__ __forceinline__ void cp16(uint32_t smem_addr, const void* g) {
    asm volatile("cp.async.ca.shared.global [%0], [%1], 16;"
                 :: "r"(smem_addr), "l"(g));
}
#define CP_COMMIT() asm volatile("cp.async.commit_group;")
#define CP_WAIT0()  asm volatile("cp.async.wait_group 0;")

// ---------------------------------------------------------------------------
// Kernel 1: fused QKV projection via tf32 mma (R13 validated core) with
// SOFTWARE PREFETCH: next k-tile's LDGs issue before this tile's mma block,
// hiding gmem latency. Math/indexing bit-identical to R13.
// Q/K written as fp16 (s,d) rows; V PRE-INTERLEAVED half2 key-pairs.
// ---------------------------------------------------------------------------
__global__ __launch_bounds__(256) void proj_kernel(
    const float* __restrict__ xq, const float* __restrict__ xk, const float* __restrict__ xv,
    const float* __restrict__ wq, const float* __restrict__ wk, const float* __restrict__ wv,
    const float* __restrict__ bq, const float* __restrict__ bk, const float* __restrict__ bv,
    __half* __restrict__ stage)
{
    const int which = blockIdx.z;
    const float* X  = (which == 0) ? xq : (which == 1) ? xk : xv;
    const float* W  = (which == 0) ? wq : (which == 1) ? wk : wv;
    const float* Bi = (which == 0) ? bq : (which == 1) ? bk : bv;

    __shared__ uint32_t As[16][136];
    __shared__ uint32_t Bs[16][136];

    const int tid  = threadIdx.x;
    const int warp = tid >> 5;
    const int lane = tid & 31;
    const int gr   = lane >> 2;
    const int tg   = lane & 3;

    const int m0 = blockIdx.y * 128;
    const int n0 = blockIdx.x * 128;
    const int warp_m = (warp >> 2) * 64;
    const int warp_n = (warp & 3) * 32;

    const int a_r = tid >> 1;
    const int a_kc = (tid & 1) * 8;
    const int b_kr = tid >> 4;
    const int b_nc = (tid & 15) * 8;

    const float* Xp = &X[(size_t)(m0 + a_r) * DMOD + a_kc];
    const float* Wp = &W[(size_t)b_kr * DMOD + n0 + b_nc];

    float acc[4][4][4];
#pragma unroll
    for (int mt = 0; mt < 4; mt++)
#pragma unroll
        for (int nt = 0; nt < 4; nt++)
#pragma unroll
            for (int r = 0; r < 4; r++) acc[mt][nt][r] = 0.f;

    // preload k-tile 0
    float4 x0 = *(const float4*)&Xp[0];
    float4 x1 = *(const float4*)&Xp[4];
    float4 w0 = *(const float4*)&Wp[0];
    float4 w1 = *(const float4*)&Wp[4];

    for (int k0 = 0; k0 < DMOD; k0 += 16) {
        __syncthreads();
        As[a_kc + 0][a_r] = f2tf(x0.x);
        As[a_kc + 1][a_r] = f2tf(x0.y);
        As[a_kc + 2][a_r] = f2tf(x0.z);
        As[a_kc + 3][a_r] = f2tf(x0.w);
        As[a_kc + 4][a_r] = f2tf(x1.x);
        As[a_kc + 5][a_r] = f2tf(x1.y);
        As[a_kc + 6][a_r] = f2tf(x1.z);
        As[a_kc + 7][a_r] = f2tf(x1.w);
        Bs[b_kr][b_nc + 0] = f2tf(w0.x);
        Bs[b_kr][b_nc + 1] = f2tf(w0.y);
        Bs[b_kr][b_nc + 2] = f2tf(w0.z);
        Bs[b_kr][b_nc + 3] = f2tf(w0.w);
        Bs[b_kr][b_nc + 4] = f2tf(w1.x);
        Bs[b_kr][b_nc + 5] = f2tf(w1.y);
        Bs[b_kr][b_nc + 6] = f2tf(w1.z);
        Bs[b_kr][b_nc + 7] = f2tf(w1.w);
        __syncthreads();

        // prefetch next k-tile while mma runs
        if (k0 + 16 < DMOD) {
            x0 = *(const float4*)&Xp[k0 + 16];
            x1 = *(const float4*)&Xp[k0 + 20];
            w0 = *(const float4*)&Wp[(size_t)(k0 + 16) * DMOD];
            w1 = *(const float4*)&Wp[(size_t)(k0 + 16) * DMOD + 4];
        }

#pragma unroll
        for (int kk = 0; kk < 16; kk += 8) {
            uint32_t af[4][4], bf[4][2];
#pragma unroll
            for (int mt = 0; mt < 4; mt++) {
                const int mm = warp_m + mt * 16 + gr;
                af[mt][0] = As[kk + tg][mm];
                af[mt][1] = As[kk + tg][mm + 8];
                af[mt][2] = As[kk + tg + 4][mm];
                af[mt][3] = As[kk + tg + 4][mm + 8];
            }
#pragma unroll
            for (int nt = 0; nt < 4; nt++) {
                const int nn = warp_n + nt * 8 + gr;
                bf[nt][0] = Bs[kk + tg][nn];
                bf[nt][1] = Bs[kk + tg + 4][nn];
            }
#pragma unroll
            for (int mt = 0; mt < 4; mt++)
#pragma unroll
                for (int nt = 0; nt < 4; nt++)
                    mma_tf32(acc[mt][nt], af[mt], bf[nt]);
        }
    }

    const int h  = (n0 + warp_n) >> 6;
    const int bb = m0 >> 11;
    const int bh = bb * NH + h;
    const int d_base = ((n0 + warp_n) & 63);
    const int ss_base = (m0 & (SEQ - 1)) + warp_m;

    __half* dst = (bh < NSPLIT)
        ? stage + (size_t)which * ((size_t)NSPLIT * PBH) + (size_t)bh * PBH
        : g_tail + (size_t)which * (6 * PBH) + (size_t)(bh - NSPLIT) * PBH;

#pragma unroll
    for (int nt = 0; nt < 4; nt++) {
        const int ncol = n0 + warp_n + nt * 8 + 2 * tg;
        const float bias0 = Bi[ncol];
        const float bias1 = Bi[ncol + 1];
        const int d = d_base + nt * 8 + 2 * tg;
#pragma unroll
        for (int mt = 0; mt < 4; mt++) {
            const int s0 = ss_base + mt * 16 + gr;
            const int s1 = s0 + 8;
            if (which == 2) {
                // V: interleaved half2 key-pair layout
                dst[(size_t)(s0 >> 1) * (2 * DH) + 2 * d + (s0 & 1)] =
                    __float2half(acc[mt][nt][0] + bias0);
                dst[(size_t)(s0 >> 1) * (2 * DH) + 2 * (d + 1) + (s0 & 1)] =
                    __float2half(acc[mt][nt][1] + bias1);
                dst[(size_t)(s1 >> 1) * (2 * DH) + 2 * d + (s1 & 1)] =
                    __float2half(acc[mt][nt][2] + bias0);
                dst[(size_t)(s1 >> 1) * (2 * DH) + 2 * (d + 1) + (s1 & 1)] =
                    __float2half(acc[mt][nt][3] + bias1);
            } else {
                __half2 v0 = __floats2half2_rn(acc[mt][nt][0] + bias0, acc[mt][nt][1] + bias1);
                __half2 v1 = __floats2half2_rn(acc[mt][nt][2] + bias0, acc[mt][nt][3] + bias1);
                *(__half2*)&dst[(size_t)s0 * DH + d] = v0;
                *(__half2*)&dst[(size_t)s1 * DH + d] = v1;
            }
        }
    }
}

// ---------------------------------------------------------------------------
// Kernel 2: FUSED attention, all-fp16 tensor ops + cp.async double buffering.
// (byte-identical to R13 — validated)
// smem layout (words), per buffer: K[128*36] | V[64*72] | M[128*36]
// ---------------------------------------------------------------------------
#define KW 36
#define VW 72
#define MW 36
#define KBUF (128 * KW)
#define VBUF (64 * VW)
#define MBUF (128 * MW)
#define TBUF (KBUF + VBUF + MBUF)
#define SMEM_WORDS (2 * TBUF)

__global__ __launch_bounds__(256, 2) void fused_attn_kernel(
    const unsigned char* __restrict__ mask, float* __restrict__ attn,
    float* __restrict__ ctx, const __half* __restrict__ stage, int bh0)
{
    extern __shared__ uint32_t smem[];

    const int bh = bh0 + blockIdx.y;
    const int m0 = blockIdx.x * 128;
    const int b = bh >> 4, h = bh & 15;

    const __half* Q = (bh < NSPLIT)
        ? stage + (size_t)bh * PBH
        : g_tail + (size_t)(bh - NSPLIT) * PBH;
    const __half* K = (bh < NSPLIT)
        ? stage + (size_t)NSPLIT * PBH + (size_t)bh * PBH
        : g_tail + (size_t)(6 * PBH) + (size_t)(bh - NSPLIT) * PBH;
    const __half* V = (bh < NSPLIT)
        ? stage + (size_t)(2 * NSPLIT) * PBH + (size_t)bh * PBH
        : g_tail + (size_t)(12 * PBH) + (size_t)(bh - NSPLIT) * PBH;

    const int tid  = threadIdx.x;
    const int warp = tid >> 5;
    const int lane = tid & 31;
    const int gr   = lane >> 2;
    const int tg   = lane & 3;

    const int r0 = warp * 16 + gr;
    const int r1 = r0 + 8;

    const uint32_t smem_base = (uint32_t)__cvta_generic_to_shared(smem);

    uint32_t qf[4][4];
#pragma unroll
    for (int kc = 0; kc < 4; kc++) {
        qf[kc][0] = *(const uint32_t*)&Q[(size_t)(m0 + r0) * DH + (kc * 8 + tg) * 2];
        qf[kc][1] = *(const uint32_t*)&Q[(size_t)(m0 + r1) * DH + (kc * 8 + tg) * 2];
        qf[kc][2] = *(const uint32_t*)&Q[(size_t)(m0 + r0) * DH + (kc * 8 + tg + 4) * 2];
        qf[kc][3] = *(const uint32_t*)&Q[(size_t)(m0 + r1) * DH + (kc * 8 + tg + 4) * 2];
    }

    float rsum0 = 0.f, rsum1 = 0.f;
    float ctxacc[8][4];
#pragma unroll
    for (int dt = 0; dt < 8; dt++)
#pragma unroll
        for (int r = 0; r < 4; r++) ctxacc[dt][r] = 0.f;

    float* arow0 = attn + ((size_t)bh * SEQ + m0 + r0) * SEQ;
    float* arow1 = attn + ((size_t)bh * SEQ + m0 + r1) * SEQ;

    const int k_row = tid >> 1;
    const int k_cw  = (tid & 1) * 16;
    const int v_row = tid >> 2;
    const int v_cw  = (tid & 3) * 16;
    const int m_row = tid >> 1;
    const int m_cb  = (tid & 1) * 64;

    const unsigned char* mask_base = mask + ((size_t)b * SEQ + m0) * SEQ;

    auto load_tile = [&](int kt, int buf) {
        const uint32_t boff = smem_base + buf * (TBUF * 4);
        {
            const __half* src = K + (size_t)(kt * 128 + k_row) * DH + k_cw * 2;
            uint32_t dst = boff + (k_row * KW + k_cw) * 4;
            cp16(dst, src);
            cp16(dst + 16, src + 8);
            cp16(dst + 32, src + 16);
            cp16(dst + 48, src + 24);
        }
        {
            const __half* src = V + (size_t)(kt * 64 + v_row) * (2 * DH) + v_cw * 2;
            uint32_t dst = boff + (KBUF + v_row * VW + v_cw) * 4;
            cp16(dst, src);
            cp16(dst + 16, src + 8);
            cp16(dst + 32, src + 16);
            cp16(dst + 48, src + 24);
        }
        {
            const unsigned char* src = mask_base + (size_t)m_row * SEQ + kt * 128 + m_cb;
            uint32_t dst = boff + (KBUF + VBUF + m_row * MW) * 4 + m_cb;
            cp16(dst, src);
            cp16(dst + 16, src + 16);
            cp16(dst + 32, src + 32);
            cp16(dst + 48, src + 48);
        }
        CP_COMMIT();
    };

    load_tile(0, 0);
    int buf = 0;

    for (int kt = 0; kt < 16; kt++) {
        CP_WAIT0();
        __syncthreads();
        if (kt < 15) load_tile(kt + 1, buf ^ 1);

        const uint32_t* Kh = smem + buf * TBUF;
        const uint32_t* Vh = Kh + KBUF;
        const unsigned char* Mh = (const unsigned char*)(Vh + VBUF);

#pragma unroll
        for (int hk = 0; hk < 2; hk++) {
            const int kbase = hk * 64;

            float sacc[8][4];
#pragma unroll
            for (int nt = 0; nt < 8; nt++)
#pragma unroll
                for (int r = 0; r < 4; r++) sacc[nt][r] = 0.f;

#pragma unroll
            for (int kc = 0; kc < 4; kc++) {
#pragma unroll
                for (int nt = 0; nt < 8; nt++) {
                    uint32_t bf[2];
                    bf[0] = Kh[(kbase + nt * 8 + gr) * KW + kc * 8 + tg];
                    bf[1] = Kh[(kbase + nt * 8 + gr) * KW + kc * 8 + tg + 4];
                    mma_f16(sacc[nt], qf[kc], bf);
                }
            }

            const int colb = kt * 128 + kbase;
#pragma unroll
            for (int nt = 0; nt < 8; nt++) {
                const int lcol = kbase + nt * 8 + 2 * tg;
                const int col  = colb + nt * 8 + 2 * tg;
                uchar2 mm0 = *(const uchar2*)&Mh[(size_t)r0 * (MW * 4) + lcol];
                uchar2 mm1 = *(const uchar2*)&Mh[(size_t)r1 * (MW * 4) + lcol];
                float s00 = mm0.x ? -1e9f : sacc[nt][0] * 0.125f;
                float s01 = mm0.y ? -1e9f : sacc[nt][1] * 0.125f;
                float s10 = mm1.x ? -1e9f : sacc[nt][2] * 0.125f;
                float s11 = mm1.y ? -1e9f : sacc[nt][3] * 0.125f;
                float p00 = __expf(s00), p01 = __expf(s01);
                float p10 = __expf(s10), p11 = __expf(s11);
                rsum0 += p00 + p01;
                rsum1 += p10 + p11;
                sacc[nt][0] = p00; sacc[nt][1] = p01;
                sacc[nt][2] = p10; sacc[nt][3] = p11;
                *(float2*)&arow0[col] = make_float2(p00, p01);
                *(float2*)&arow1[col] = make_float2(p10, p11);
            }

#pragma unroll
            for (int g = 0; g < 4; g++) {
                uint32_t pa[4];
                pa[0] = pack_h2(sacc[2 * g][0],     sacc[2 * g][1]);
                pa[1] = pack_h2(sacc[2 * g][2],     sacc[2 * g][3]);
                pa[2] = pack_h2(sacc[2 * g + 1][0], sacc[2 * g + 1][1]);
                pa[3] = pack_h2(sacc[2 * g + 1][2], sacc[2 * g + 1][3]);
#pragma unroll
                for (int dt = 0; dt < 8; dt++) {
                    uint32_t vb[2];
                    vb[0] = Vh[(hk * 32 + g * 8 + tg) * VW + dt * 8 + gr];
                    vb[1] = Vh[(hk * 32 + g * 8 + tg + 4) * VW + dt * 8 + gr];
                    mma_f16(ctxacc[dt], pa, vb);
                }
            }
        }
        __syncthreads();
        buf ^= 1;
    }

    rsum0 += __shfl_xor_sync(0xffffffffu, rsum0, 1);
    rsum0 += __shfl_xor_sync(0xffffffffu, rsum0, 2);
    rsum1 += __shfl_xor_sync(0xffffffffu, rsum1, 1);
    rsum1 += __shfl_xor_sync(0xffffffffu, rsum1, 2);
    if (tg == 0) {
        g_sums[(size_t)bh * SEQ + m0 + r0] = rsum0;
        g_sums[(size_t)bh * SEQ + m0 + r1] = rsum1;
    }
    const float inv0 = 1.0f / rsum0;
    const float inv1 = 1.0f / rsum1;

    float* crow0 = ctx + ((size_t)b * SEQ + m0 + r0) * DMOD + h * DH;
    float* crow1 = ctx + ((size_t)b * SEQ + m0 + r1) * DMOD + h * DH;
#pragma unroll
    for (int dt = 0; dt < 8; dt++) {
        const int d = dt * 8 + 2 * tg;
        *(float2*)&crow0[d] = make_float2(ctxacc[dt][0] * inv0, ctxacc[dt][1] * inv0);
        *(float2*)&crow1[d] = make_float2(ctxacc[dt][2] * inv1, ctxacc[dt][3] * inv1);
    }
}

// ---------------------------------------------------------------------------
// Kernel 3: scale attn rows by 1/rowsum (at DRAM roofline; unchanged).
// ---------------------------------------------------------------------------
__global__ __launch_bounds__(256) void scale_kernel(float* __restrict__ attn)
{
    const size_t row = blockIdx.x;
    const float inv = 1.0f / g_sums[row];
    float* p = attn + row * SEQ;
    const int tid = threadIdx.x;
    float4 v0 = *(float4*)&p[tid * 4];
    float4 v1 = *(float4*)&p[1024 + tid * 4];
    v0.x *= inv; v0.y *= inv; v0.z *= inv; v0.w *= inv;
    v1.x *= inv; v1.y *= inv; v1.z *= inv; v1.w *= inv;
    *(float4*)&p[tid * 4] = v0;
    *(float4*)&p[1024 + tid * 4] = v1;
}

// ---------------------------------------------------------------------------
// Launch. Output: [context (4,2048,1024) | attn (4,16,2048,2048)] fp32.
// Q/K/V (fp16) for bh<58 staged in attn slices 58..63; bh>=58 in g_tail.
// ---------------------------------------------------------------------------
extern "C" void kernel_launch(void* const* d_in, const int* in_sizes, int n_in,
                              void* d_out, int out_size)
{
    (void)in_sizes; (void)n_in; (void)out_size;
    const float* q  = (const float*)d_in[0];
    const float* k  = (const float*)d_in[1];
    const float* v  = (const float*)d_in[2];
    const unsigned char* mask = (const unsigned char*)d_in[3];
    const float* wq = (const float*)d_in[4];
    const float* wk = (const float*)d_in[5];
    const float* wv = (const float*)d_in[6];
    const float* bq = (const float*)d_in[7];
    const float* bk = (const float*)d_in[8];
    const float* bv = (const float*)d_in[9];

    float* ctx   = (float*)d_out;
    float* attn  = (float*)d_out + (size_t)NB * SEQ * DMOD;
    __half* stage = (__half*)(attn + (size_t)NSPLIT * SL);   // slices 58..63

    const int smem_bytes = SMEM_WORDS * 4;   // 110592 B
    cudaFuncSetAttribute(fused_attn_kernel,
                         cudaFuncAttributeMaxDynamicSharedMemorySize, smem_bytes);

    // 1) QKV projections into fp16 staging (V interleaved)
    {
        dim3 grid(DMOD / 128, (NB * SEQ) / 128, 3);
        proj_kernel<<<grid, 256>>>(q, k, v, wq, wk, wv, bq, bk, bv, stage);
    }
    // 2) Phase A: fused attention for bh 0..57
    {
        dim3 grid(SEQ / 128, NSPLIT);
        fused_attn_kernel<<<grid, 256, smem_bytes>>>(mask, attn, ctx, stage, 0);
    }
    // 3) Phase B: fused attention for bh 58..63 (QKV in g_tail)
    {
        dim3 grid(SEQ / 128, BHN - NSPLIT);
        fused_attn_kernel<<<grid, 256, smem_bytes>>>(mask, attn, ctx, stage, NSPLIT);
    }
    // 4) Normalize the attn output
    scale_kernel<<<BHN * SEQ, 256>>>(attn);
}

// round 16
// speedup vs baseline: 1.0314x; 1.0182x over previous
#include <cuda_runtime.h>
#include <cuda_fp16.h>
#include <cstdint>

#define NB   4
#define NH   16
#define SEQ  2048
#define DMOD 1024
#define DH   64
#define BHN  (NB * NH)        // 64
#define SL   4194304          // floats per attn slice (2048*2048)
#define PBH  131072           // ELEMENTS per (bh) Q/K/V slab (2048*64), fp16
#define NSPLIT 58             // bh 0..57 staged in d_out, 58..63 in g_tail

// Scratch: 6 tail (bh) Q/K/V slabs (4.7 MB, fp16) + row sums (0.5 MB).
static __device__ __half g_tail[18 * PBH];
static __device__ float g_sums[(size_t)BHN * SEQ];

// ---------------------------------------------------------------------------
// helpers
// ---------------------------------------------------------------------------
__device__ __forceinline__ uint32_t f2tf(float f) {
    uint32_t u;
    asm("cvt.rna.tf32.f32 %0, %1;" : "=r"(u) : "f"(f));
    return u;
}

__device__ __forceinline__ uint32_t pack_h2(float lo, float hi) {
    __half2 h = __floats2half2_rn(lo, hi);
    return *reinterpret_cast<uint32_t*>(&h);
}

__device__ __forceinline__ void mma_tf32(float* c, const uint32_t* a, const uint32_t* b) {
    asm volatile(
        "mma.sync.aligned.m16n8k8.row.col.f32.tf32.tf32.f32 "
        "{%0,%1,%2,%3}, {%4,%5,%6,%7}, {%8,%9}, {%0,%1,%2,%3};"
        : "+f"(c[0]), "+f"(c[1]), "+f"(c[2]), "+f"(c[3])
        : "r"(a[0]), "r"(a[1]), "r"(a[2]), "r"(a[3]), "r"(b[0]), "r"(b[1]));
}

__device__ __forceinline__ void mma_f16(float* c, const uint32_t* a, const uint32_t* b) {
    asm volatile(
        "mma.sync.aligned.m16n8k16.row.col.f32.f16.f16.f32 "
        "{%0,%1,%2,%3}, {%4,%5,%6,%7}, {%8,%9}, {%0,%1,%2,%3};"
        : "+f"(c[0]), "+f"(c[1]), "+f"(c[2]), "+f"(c[3])
        : "r"(a[0]), "r"(a[1]), "r"(a[2]), "r"(a[3]), "r"(b[0]), "r"(b[1]));
}

__device__ __forceinline__ void ldsm_x4(uint32_t& d0, uint32_t& d1,
                                        uint32_t& d2, uint32_t& d3, uint32_t addr) {
    asm volatile("ldmatrix.sync.aligned.m8n8.x4.shared.b16 {%0,%1,%2,%3}, [%4];"
                 : "=r"(d0), "=r"(d1), "=r"(d2), "=r"(d3) : "r"(addr));
}

__device__ __forceinline__ void cp16(uint32_t smem_addr, const void* g) {
    asm volatile("cp.async.ca.shared.global [%0], [%1], 16;"
                 :: "r"(smem_addr), "l"(g));
}
#define CP_COMMIT() asm volatile("cp.async.commit_group;")
#define CP_WAIT0()  asm volatile("cp.async.wait_group 0;")

// ---------------------------------------------------------------------------
// Kernel 1: fused QKV projection via tf32 mma (R13 validated core, exact).
// Q/K written as fp16 (s,d) rows; V PRE-INTERLEAVED half2 key-pairs.
// ---------------------------------------------------------------------------
__global__ __launch_bounds__(256) void proj_kernel(
    const float* __restrict__ xq, const float* __restrict__ xk, const float* __restrict__ xv,
    const float* __restrict__ wq, const float* __restrict__ wk, const float* __restrict__ wv,
    const float* __restrict__ bq, const float* __restrict__ bk, const float* __restrict__ bv,
    __half* __restrict__ stage)
{
    const int which = blockIdx.z;
    const float* X  = (which == 0) ? xq : (which == 1) ? xk : xv;
    const float* W  = (which == 0) ? wq : (which == 1) ? wk : wv;
    const float* Bi = (which == 0) ? bq : (which == 1) ? bk : bv;

    __shared__ uint32_t As[16][136];
    __shared__ uint32_t Bs[16][136];

    const int tid  = threadIdx.x;
    const int warp = tid >> 5;
    const int lane = tid & 31;
    const int gr   = lane >> 2;
    const int tg   = lane & 3;

    const int m0 = blockIdx.y * 128;
    const int n0 = blockIdx.x * 128;
    const int warp_m = (warp >> 2) * 64;
    const int warp_n = (warp & 3) * 32;

    const int a_r = tid >> 1;
    const int a_kc = (tid & 1) * 8;
    const int b_kr = tid >> 4;
    const int b_nc = (tid & 15) * 8;

    float acc[4][4][4];
#pragma unroll
    for (int mt = 0; mt < 4; mt++)
#pragma unroll
        for (int nt = 0; nt < 4; nt++)
#pragma unroll
            for (int r = 0; r < 4; r++) acc[mt][nt][r] = 0.f;

    for (int k0 = 0; k0 < DMOD; k0 += 16) {
        float4 x0 = *(const float4*)&X[(size_t)(m0 + a_r) * DMOD + k0 + a_kc];
        float4 x1 = *(const float4*)&X[(size_t)(m0 + a_r) * DMOD + k0 + a_kc + 4];
        float4 w0 = *(const float4*)&W[(size_t)(k0 + b_kr) * DMOD + n0 + b_nc];
        float4 w1 = *(const float4*)&W[(size_t)(k0 + b_kr) * DMOD + n0 + b_nc + 4];
        __syncthreads();
        As[a_kc + 0][a_r] = f2tf(x0.x);
        As[a_kc + 1][a_r] = f2tf(x0.y);
        As[a_kc + 2][a_r] = f2tf(x0.z);
        As[a_kc + 3][a_r] = f2tf(x0.w);
        As[a_kc + 4][a_r] = f2tf(x1.x);
        As[a_kc + 5][a_r] = f2tf(x1.y);
        As[a_kc + 6][a_r] = f2tf(x1.z);
        As[a_kc + 7][a_r] = f2tf(x1.w);
        Bs[b_kr][b_nc + 0] = f2tf(w0.x);
        Bs[b_kr][b_nc + 1] = f2tf(w0.y);
        Bs[b_kr][b_nc + 2] = f2tf(w0.z);
        Bs[b_kr][b_nc + 3] = f2tf(w0.w);
        Bs[b_kr][b_nc + 4] = f2tf(w1.x);
        Bs[b_kr][b_nc + 5] = f2tf(w1.y);
        Bs[b_kr][b_nc + 6] = f2tf(w1.z);
        Bs[b_kr][b_nc + 7] = f2tf(w1.w);
        __syncthreads();

#pragma unroll
        for (int kk = 0; kk < 16; kk += 8) {
            uint32_t af[4][4], bf[4][2];
#pragma unroll
            for (int mt = 0; mt < 4; mt++) {
                const int mm = warp_m + mt * 16 + gr;
                af[mt][0] = As[kk + tg][mm];
                af[mt][1] = As[kk + tg][mm + 8];
                af[mt][2] = As[kk + tg + 4][mm];
                af[mt][3] = As[kk + tg + 4][mm + 8];
            }
#pragma unroll
            for (int nt = 0; nt < 4; nt++) {
                const int nn = warp_n + nt * 8 + gr;
                bf[nt][0] = Bs[kk + tg][nn];
                bf[nt][1] = Bs[kk + tg + 4][nn];
            }
#pragma unroll
            for (int mt = 0; mt < 4; mt++)
#pragma unroll
                for (int nt = 0; nt < 4; nt++)
                    mma_tf32(acc[mt][nt], af[mt], bf[nt]);
        }
    }

    const int h  = (n0 + warp_n) >> 6;
    const int bb = m0 >> 11;
    const int bh = bb * NH + h;
    const int d_base = ((n0 + warp_n) & 63);
    const int ss_base = (m0 & (SEQ - 1)) + warp_m;

    __half* dst = (bh < NSPLIT)
        ? stage + (size_t)which * ((size_t)NSPLIT * PBH) + (size_t)bh * PBH
        : g_tail + (size_t)which * (6 * PBH) + (size_t)(bh - NSPLIT) * PBH;

#pragma unroll
    for (int nt = 0; nt < 4; nt++) {
        const int ncol = n0 + warp_n + nt * 8 + 2 * tg;
        const float bias0 = Bi[ncol];
        const float bias1 = Bi[ncol + 1];
        const int d = d_base + nt * 8 + 2 * tg;
#pragma unroll
        for (int mt = 0; mt < 4; mt++) {
            const int s0 = ss_base + mt * 16 + gr;
            const int s1 = s0 + 8;
            if (which == 2) {
                // V: interleaved half2 key-pair layout
                dst[(size_t)(s0 >> 1) * (2 * DH) + 2 * d + (s0 & 1)] =
                    __float2half(acc[mt][nt][0] + bias0);
                dst[(size_t)(s0 >> 1) * (2 * DH) + 2 * (d + 1) + (s0 & 1)] =
                    __float2half(acc[mt][nt][1] + bias1);
                dst[(size_t)(s1 >> 1) * (2 * DH) + 2 * d + (s1 & 1)] =
                    __float2half(acc[mt][nt][2] + bias0);
                dst[(size_t)(s1 >> 1) * (2 * DH) + 2 * (d + 1) + (s1 & 1)] =
                    __float2half(acc[mt][nt][3] + bias1);
            } else {
                __half2 v0 = __floats2half2_rn(acc[mt][nt][0] + bias0, acc[mt][nt][1] + bias1);
                __half2 v1 = __floats2half2_rn(acc[mt][nt][2] + bias0, acc[mt][nt][3] + bias1);
                *(__half2*)&dst[(size_t)s0 * DH + d] = v0;
                *(__half2*)&dst[(size_t)s1 * DH + d] = v1;
            }
        }
    }
}

// ---------------------------------------------------------------------------
// Kernel 2: FUSED attention, all-fp16 tensor ops + cp.async double buffering
// + ldmatrix.x4 K-fragment loads (128 LDS.32 -> 32 LDSM per tile per warp).
// smem layout (words), per buffer: K[128*36] | V[64*72] | M[128*36]
// ---------------------------------------------------------------------------
#define KW 36
#define VW 72
#define MW 36
#define KBUF (128 * KW)
#define VBUF (64 * VW)
#define MBUF (128 * MW)
#define TBUF (KBUF + VBUF + MBUF)
#define SMEM_WORDS (2 * TBUF)

__global__ __launch_bounds__(256, 2) void fused_attn_kernel(
    const unsigned char* __restrict__ mask, float* __restrict__ attn,
    float* __restrict__ ctx, const __half* __restrict__ stage, int bh0)
{
    extern __shared__ uint32_t smem[];

    const int bh = bh0 + blockIdx.y;
    const int m0 = blockIdx.x * 128;
    const int b = bh >> 4, h = bh & 15;

    const __half* Q = (bh < NSPLIT)
        ? stage + (size_t)bh * PBH
        : g_tail + (size_t)(bh - NSPLIT) * PBH;
    const __half* K = (bh < NSPLIT)
        ? stage + (size_t)NSPLIT * PBH + (size_t)bh * PBH
        : g_tail + (size_t)(6 * PBH) + (size_t)(bh - NSPLIT) * PBH;
    const __half* V = (bh < NSPLIT)
        ? stage + (size_t)(2 * NSPLIT) * PBH + (size_t)bh * PBH
        : g_tail + (size_t)(12 * PBH) + (size_t)(bh - NSPLIT) * PBH;

    const int tid  = threadIdx.x;
    const int warp = tid >> 5;
    const int lane = tid & 31;
    const int gr   = lane >> 2;
    const int tg   = lane & 3;
    const int lrow  = lane & 7;    // ldmatrix row within 8-row matrix
    const int lquad = lane >> 3;   // ldmatrix matrix index 0..3

    const int r0 = warp * 16 + gr;
    const int r1 = r0 + 8;

    const uint32_t smem_base = (uint32_t)__cvta_generic_to_shared(smem);

    uint32_t qf[4][4];
#pragma unroll
    for (int kc = 0; kc < 4; kc++) {
        qf[kc][0] = *(const uint32_t*)&Q[(size_t)(m0 + r0) * DH + (kc * 8 + tg) * 2];
        qf[kc][1] = *(const uint32_t*)&Q[(size_t)(m0 + r1) * DH + (kc * 8 + tg) * 2];
        qf[kc][2] = *(const uint32_t*)&Q[(size_t)(m0 + r0) * DH + (kc * 8 + tg + 4) * 2];
        qf[kc][3] = *(const uint32_t*)&Q[(size_t)(m0 + r1) * DH + (kc * 8 + tg + 4) * 2];
    }

    float rsum0 = 0.f, rsum1 = 0.f;
    float ctxacc[8][4];
#pragma unroll
    for (int dt = 0; dt < 8; dt++)
#pragma unroll
        for (int r = 0; r < 4; r++) ctxacc[dt][r] = 0.f;

    float* arow0 = attn + ((size_t)bh * SEQ + m0 + r0) * SEQ;
    float* arow1 = attn + ((size_t)bh * SEQ + m0 + r1) * SEQ;

    const int k_row = tid >> 1;
    const int k_cw  = (tid & 1) * 16;
    const int v_row = tid >> 2;
    const int v_cw  = (tid & 3) * 16;
    const int m_row = tid >> 1;
    const int m_cb  = (tid & 1) * 64;

    const unsigned char* mask_base = mask + ((size_t)b * SEQ + m0) * SEQ;

    auto load_tile = [&](int kt, int buf) {
        const uint32_t boff = smem_base + buf * (TBUF * 4);
        {
            const __half* src = K + (size_t)(kt * 128 + k_row) * DH + k_cw * 2;
            uint32_t dst = boff + (k_row * KW + k_cw) * 4;
            cp16(dst, src);
            cp16(dst + 16, src + 8);
            cp16(dst + 32, src + 16);
            cp16(dst + 48, src + 24);
        }
        {
            const __half* src = V + (size_t)(kt * 64 + v_row) * (2 * DH) + v_cw * 2;
            uint32_t dst = boff + (KBUF + v_row * VW + v_cw) * 4;
            cp16(dst, src);
            cp16(dst + 16, src + 8);
            cp16(dst + 32, src + 16);
            cp16(dst + 48, src + 24);
        }
        {
            const unsigned char* src = mask_base + (size_t)m_row * SEQ + kt * 128 + m_cb;
            uint32_t dst = boff + (KBUF + VBUF + m_row * MW) * 4 + m_cb;
            cp16(dst, src);
            cp16(dst + 16, src + 16);
            cp16(dst + 32, src + 32);
            cp16(dst + 48, src + 48);
        }
        CP_COMMIT();
    };

    load_tile(0, 0);
    int buf = 0;

    for (int kt = 0; kt < 16; kt++) {
        CP_WAIT0();
        __syncthreads();
        if (kt < 15) load_tile(kt + 1, buf ^ 1);

        const uint32_t* Vh = smem + buf * TBUF + KBUF;
        const unsigned char* Mh = (const unsigned char*)(Vh + VBUF);
        const uint32_t kh_base = smem_base + buf * (TBUF * 4);

#pragma unroll
        for (int hk = 0; hk < 2; hk++) {
            const int kbase = hk * 64;

            // --- S = Q K^T (fp16) via ldmatrix.x4 K-fragments ---
            float sacc[8][4];
#pragma unroll
            for (int nt = 0; nt < 8; nt++)
#pragma unroll
                for (int r = 0; r < 4; r++) sacc[nt][r] = 0.f;

#pragma unroll
            for (int nt = 0; nt < 8; nt++) {
                const uint32_t rowaddr =
                    kh_base + (((kbase + nt * 8 + lrow) * KW) + lquad * 4) * 4;
                uint32_t d0, d1, d2, d3;
                ldsm_x4(d0, d1, d2, d3, rowaddr);          // kc 0,1
                {
                    uint32_t bf[2] = {d0, d1};
                    mma_f16(sacc[nt], qf[0], bf);
                }
                {
                    uint32_t bf[2] = {d2, d3};
                    mma_f16(sacc[nt], qf[1], bf);
                }
                ldsm_x4(d0, d1, d2, d3, rowaddr + 64);     // kc 2,3 (+16 words)
                {
                    uint32_t bf[2] = {d0, d1};
                    mma_f16(sacc[nt], qf[2], bf);
                }
                {
                    uint32_t bf[2] = {d2, d3};
                    mma_f16(sacc[nt], qf[3], bf);
                }
            }

            // --- scale, mask (from smem), exp, rowsum, write p ---
            const int colb = kt * 128 + kbase;
#pragma unroll
            for (int nt = 0; nt < 8; nt++) {
                const int lcol = kbase + nt * 8 + 2 * tg;
                const int col  = colb + nt * 8 + 2 * tg;
                uchar2 mm0 = *(const uchar2*)&Mh[(size_t)r0 * (MW * 4) + lcol];
                uchar2 mm1 = *(const uchar2*)&Mh[(size_t)r1 * (MW * 4) + lcol];
                float s00 = mm0.x ? -1e9f : sacc[nt][0] * 0.125f;
                float s01 = mm0.y ? -1e9f : sacc[nt][1] * 0.125f;
                float s10 = mm1.x ? -1e9f : sacc[nt][2] * 0.125f;
                float s11 = mm1.y ? -1e9f : sacc[nt][3] * 0.125f;
                float p00 = __expf(s00), p01 = __expf(s01);
                float p10 = __expf(s10), p11 = __expf(s11);
                rsum0 += p00 + p01;
                rsum1 += p10 + p11;
                sacc[nt][0] = p00; sacc[nt][1] = p01;
                sacc[nt][2] = p10; sacc[nt][3] = p11;
                *(float2*)&arow0[col] = make_float2(p00, p01);
                *(float2*)&arow1[col] = make_float2(p10, p11);
            }

            // --- ctx += p @ V (fp16, in-thread C->A fragment reuse) ---
#pragma unroll
            for (int g = 0; g < 4; g++) {
                uint32_t pa[4];
                pa[0] = pack_h2(sacc[2 * g][0],     sacc[2 * g][1]);
                pa[1] = pack_h2(sacc[2 * g][2],     sacc[2 * g][3]);
                pa[2] = pack_h2(sacc[2 * g + 1][0], sacc[2 * g + 1][1]);
                pa[3] = pack_h2(sacc[2 * g + 1][2], sacc[2 * g + 1][3]);
#pragma unroll
                for (int dt = 0; dt < 8; dt++) {
                    uint32_t vb[2];
                    vb[0] = Vh[(hk * 32 + g * 8 + tg) * VW + dt * 8 + gr];
                    vb[1] = Vh[(hk * 32 + g * 8 + tg + 4) * VW + dt * 8 + gr];
                    mma_f16(ctxacc[dt], pa, vb);
                }
            }
        }
        __syncthreads();
        buf ^= 1;
    }

    rsum0 += __shfl_xor_sync(0xffffffffu, rsum0, 1);
    rsum0 += __shfl_xor_sync(0xffffffffu, rsum0, 2);
    rsum1 += __shfl_xor_sync(0xffffffffu, rsum1, 1);
    rsum1 += __shfl_xor_sync(0xffffffffu, rsum1, 2);
    if (tg == 0) {
        g_sums[(size_t)bh * SEQ + m0 + r0] = rsum0;
        g_sums[(size_t)bh * SEQ + m0 + r1] = rsum1;
    }
    const float inv0 = 1.0f / rsum0;
    const float inv1 = 1.0f / rsum1;

    float* crow0 = ctx + ((size_t)b * SEQ + m0 + r0) * DMOD + h * DH;
    float* crow1 = ctx + ((size_t)b * SEQ + m0 + r1) * DMOD + h * DH;
#pragma unroll
    for (int dt = 0; dt < 8; dt++) {
        const int d = dt * 8 + 2 * tg;
        *(float2*)&crow0[d] = make_float2(ctxacc[dt][0] * inv0, ctxacc[dt][1] * inv0);
        *(float2*)&crow1[d] = make_float2(ctxacc[dt][2] * inv1, ctxacc[dt][3] * inv1);
    }
}

// ---------------------------------------------------------------------------
// Kernel 3: scale attn rows by 1/rowsum (at DRAM roofline; unchanged).
// ---------------------------------------------------------------------------
__global__ __launch_bounds__(256) void scale_kernel(float* __restrict__ attn)
{
    const size_t row = blockIdx.x;
    const float inv = 1.0f / g_sums[row];
    float* p = attn + row * SEQ;
    const int tid = threadIdx.x;
    float4 v0 = *(float4*)&p[tid * 4];
    float4 v1 = *(float4*)&p[1024 + tid * 4];
    v0.x *= inv; v0.y *= inv; v0.z *= inv; v0.w *= inv;
    v1.x *= inv; v1.y *= inv; v1.z *= inv; v1.w *= inv;
    *(float4*)&p[tid * 4] = v0;
    *(float4*)&p[1024 + tid * 4] = v1;
}

// ---------------------------------------------------------------------------
// Launch. Output: [context (4,2048,1024) | attn (4,16,2048,2048)] fp32.
// Q/K/V (fp16) for bh<58 staged in attn slices 58..63; bh>=58 in g_tail.
// ---------------------------------------------------------------------------
extern "C" void kernel_launch(void* const* d_in, const int* in_sizes, int n_in,
                              void* d_out, int out_size)
{
    (void)in_sizes; (void)n_in; (void)out_size;
    const float* q  = (const float*)d_in[0];
    const float* k  = (const float*)d_in[1];
    const float* v  = (const float*)d_in[2];
    const unsigned char* mask = (const unsigned char*)d_in[3];
    const float* wq = (const float*)d_in[4];
    const float* wk = (const float*)d_in[5];
    const float* wv = (const float*)d_in[6];
    const float* bq = (const float*)d_in[7];
    const float* bk = (const float*)d_in[8];
    const float* bv = (const float*)d_in[9];

    float* ctx   = (float*)d_out;
    float* attn  = (float*)d_out + (size_t)NB * SEQ * DMOD;
    __half* stage = (__half*)(attn + (size_t)NSPLIT * SL);   // slices 58..63

    const int smem_bytes = SMEM_WORDS * 4;   // 110592 B
    cudaFuncSetAttribute(fused_attn_kernel,
                         cudaFuncAttributeMaxDynamicSharedMemorySize, smem_bytes);

    // 1) QKV projections into fp16 staging (V interleaved)
    {
        dim3 grid(DMOD / 128, (NB * SEQ) / 128, 3);
        proj_kernel<<<grid, 256>>>(q, k, v, wq, wk, wv, bq, bk, bv, stage);
    }
    // 2) Phase A: fused attention for bh 0..57
    {
        dim3 grid(SEQ / 128, NSPLIT);
        fused_attn_kernel<<<grid, 256, smem_bytes>>>(mask, attn, ctx, stage, 0);
    }
    // 3) Phase B: fused attention for bh 58..63 (QKV in g_tail)
    {
        dim3 grid(SEQ / 128, BHN - NSPLIT);
        fused_attn_kernel<<<grid, 256, smem_bytes>>>(mask, attn, ctx, stage, NSPLIT);
    }
    // 4) Normalize the attn output
    scale_kernel<<<BHN * SEQ, 256>>>(attn);
}